// round 14
// baseline (speedup 1.0000x reference)
#include <cuda_runtime.h>
#include <cstdint>

// Sparse 3D conv, persistent-CTA pipelined (mma.sync tf32; tcgen05 PTX rejected
// by harness's compute_103 target).
// out[out_map[k,m]] += feats[in_map[k,m]] @ kernel[k]
// N=200000, K=27, M=50000, Cin=Cout=64, fp32 in/out, tf32(RNA at LDS) MMA.
//
// R13 = R12 (pair-decoupled pipelines) + logical-k permutation so ALL fragment
// loads are LDS.128: physical cin c = 32h + 16q + 4t + 2s' + e maps to logical
// k-step (4h+2q+s') slot (t,e). A chunk XOR-swizzled by row parity for
// conflict-free 128-bit loads. Issue work in GEMM ~halved vs R12.

#define KOFF    27
#define MPAIRS  50000
#define NVOX    200000
#define CIN     64
#define COUT    64
#define TILE_M  128
#define NTHREADS 256
#define TPK     391                 // ceil(50000/128)
#define NTILES  (KOFF * TPK)        // 10557
#define NCTA    608                 // 4 per SM
#define QT      17                  // 10557 = 608*17 + 221
#define RT      221

#define ABUF_WORDS (TILE_M * 32)               // 4096 words per buffer (no pad)
#define OFF_B      (2 * ABUF_WORDS)            // 8192: fragment-packed W^T (4096 w)
#define OFF_IDX    (OFF_B + CIN * COUT)        // 12288: IDX[3][128]
#define OFF_OMAP   (OFF_IDX + 3 * TILE_M)      // 12672: OMAP[3][128]
#define SMEM_WORDS (OFF_OMAP + 3 * TILE_M)     // 13056 words = 52224 B

__device__ __forceinline__ uint32_t f2tf32(float f) {
    uint32_t r;
    asm("cvt.rna.tf32.f32 %0, %1;" : "=r"(r) : "f"(f));
    return r;
}
__device__ __forceinline__ void cp16(uint32_t dst, const void* src) {
    asm volatile("cp.async.cg.shared.global [%0], [%1], 16;" :: "r"(dst), "l"(src));
}
__device__ __forceinline__ void pair_bar(int id) {
    asm volatile("bar.sync %0, 64;" :: "r"(id) : "memory");
}
__device__ __forceinline__ void mma_tf32(float c[4], uint32_t a0, uint32_t a1,
                                         uint32_t a2, uint32_t a3,
                                         uint32_t b0, uint32_t b1) {
    asm volatile(
        "mma.sync.aligned.m16n8k8.row.col.f32.tf32.tf32.f32 "
        "{%0,%1,%2,%3}, {%4,%5,%6,%7}, {%8,%9}, {%0,%1,%2,%3};"
        : "+f"(c[0]), "+f"(c[1]), "+f"(c[2]), "+f"(c[3])
        : "r"(a0), "r"(a1), "r"(a2), "r"(a3), "r"(b0), "r"(b1));
}

__global__ void spconv_zero_kernel(float4* __restrict__ out, int n4) {
    int i = blockIdx.x * blockDim.x + threadIdx.x;
    if (i < n4) out[i] = make_float4(0.f, 0.f, 0.f, 0.f);
}

__global__ __launch_bounds__(NTHREADS, 4)
void spconv_pers_kernel(const float* __restrict__ feats,
                        const float* __restrict__ kern,
                        const int*   __restrict__ in_map,
                        const int*   __restrict__ out_map,
                        float*       __restrict__ out)
{
    extern __shared__ uint32_t sh[];
    const uint32_t shb = (uint32_t)__cvta_generic_to_shared(sh);

    const int tid = threadIdx.x;
    const int wid = tid >> 5;
    const int lid = tid & 31;
    const int cta = blockIdx.x;

    const int t0  = cta * QT + (cta < RT ? cta : RT);
    const int cnt = QT + (cta < RT ? 1 : 0);
    const int S   = cnt * 2;

    const int g = lid >> 2, t = lid & 3;
    const int rgrpw = wid >> 1, chalf = wid & 1;
    const int mbase = rgrpw * 32;              // pair's 32-row segment base
    const int pt    = tid & 63;                // thread index within pair
    const int barid = rgrpw + 1;               // named barrier per pair (1..4)

    // ---- Prologue: each pair fetches its idx/omap segment of tile t0 ----
    {
        int k0 = t0 / TPK, m00 = (t0 % TPK) * TILE_M;
        if (pt < 8) {
            int m = m00 + mbase + pt * 4;
            if (m < MPAIRS)
                cp16(shb + (OFF_IDX + mbase + pt * 4) * 4,
                     in_map + (size_t)k0 * MPAIRS + m);
        } else if (pt < 16) {
            int ci = pt - 8;
            int m = m00 + mbase + ci * 4;
            if (m < MPAIRS)
                cp16(shb + (OFF_OMAP + mbase + ci * 4) * 4,
                     out_map + (size_t)k0 * MPAIRS + m);
        }
        asm volatile("cp.async.commit_group;" ::: "memory");
        asm volatile("cp.async.wait_group 0;" ::: "memory");
        pair_bar(barid);
    }

    // Pair-private gather of the pair's 32 rows for stage sp (half-tile,
    // k-cols [32h, 32h+32)); chunk stored XOR-swizzled by row parity.
    auto issue_stage = [&](int sp) {
        int li = sp >> 1, h = sp & 1;
        int tt = t0 + li;
        int m0 = (tt % TPK) * TILE_M;
        int slot = li % 3;
        uint32_t abase = shb + ((sp & 1) * ABUF_WORDS) * 4;
        #pragma unroll
        for (int j = 0; j < 4; ++j) {
            int cch = pt + j * 64;             // 0..255 = 32 rows x 8 chunks
            int rl = cch >> 3, ch = cch & 7;
            int row = mbase + rl;
            int m = m0 + row;
            int gi = (int)sh[OFF_IDX + slot * TILE_M + row];
            int srow = (m < MPAIRS) ? gi : 0;
            int chs = ch ^ ((row & 1) << 2);   // conflict-free LDS.128 swizzle
            cp16(abase + row * 128 + chs * 16,
                 feats + (size_t)srow * CIN + h * 32 + ch * 4);
        }
        if (h == 0 && li + 1 < cnt) {
            int tt2 = tt + 1;
            int k2 = tt2 / TPK, m02 = (tt2 % TPK) * TILE_M;
            int slot2 = (li + 1) % 3;
            if (pt < 8) {
                int m = m02 + mbase + pt * 4;
                if (m < MPAIRS)
                    cp16(shb + (OFF_IDX + slot2 * TILE_M + mbase + pt * 4) * 4,
                         in_map + (size_t)k2 * MPAIRS + m);
            } else if (pt < 16) {
                int ci = pt - 8;
                int m = m02 + mbase + ci * 4;
                if (m < MPAIRS)
                    cp16(shb + (OFF_OMAP + slot2 * TILE_M + mbase + ci * 4) * 4,
                         out_map + (size_t)k2 * MPAIRS + m);
            }
        }
        asm volatile("cp.async.commit_group;" ::: "memory");
    };

    issue_stage(0);

    float acc[2][4][4];
    int cur_k = -1;

    // Per-thread A row base byte offsets (row-classes rc=0..3: rows mbase+8rc+g)
    uint32_t rowaddr[4];
    const int chunkxor = (g & 1) << 2;

    for (int s = 0; s < S; ++s) {
        asm volatile("cp.async.wait_group 0;" ::: "memory");
        pair_bar(barid);

        const int li = s >> 1, h = s & 1;
        const int tt = t0 + li;
        const int kk = tt / TPK;
        const int m0 = (tt % TPK) * TILE_M;

        if (h == 0) {
            if (kk != cur_k) {
                // ---- Rare CTA-wide B restage (uniform condition) ----
                __syncthreads();   // all pairs done reading old B
                const float* W = kern + (size_t)kk * CIN * COUT;
                #pragma unroll
                for (int idx = tid; idx < CIN * COUT; idx += NTHREADS) {
                    int i = idx >> 6;              // cin (physical)
                    int o = idx & 63;              // cout
                    int P = o >> 4, local = o & 15;
                    int ttq = local >> 2, rr = local & 3;
                    int pos = (2 * P + (rr >> 1)) * 8 + 2 * ttq + (rr & 1);
                    int nt = pos >> 3, gg = pos & 7;
                    int h2 = i >> 5, lc = i & 31;
                    int q = lc >> 4, tj = (lc >> 2) & 3;
                    int spr = (lc >> 1) & 1, e = lc & 1;
                    sh[OFF_B + ((nt * 4 + h2 * 2 + q) * 32 + gg * 4 + tj) * 4
                             + spr * 2 + e] = f2tf32(W[idx]);
                }
                cur_k = kk;
                __syncthreads();
            }
            #pragma unroll
            for (int mt = 0; mt < 2; ++mt)
                #pragma unroll
                for (int nt = 0; nt < 4; ++nt)
                    #pragma unroll
                    for (int e = 0; e < 4; ++e) acc[mt][nt][e] = 0.f;
        }

        if (s + 1 < S) issue_stage(s + 1);

        // ---- GEMM: all-LDS.128 fragment loads, RNA tf32 ----
        {
            uint32_t abase = shb + ((s & 1) * ABUF_WORDS) * 4;
            #pragma unroll
            for (int rc = 0; rc < 4; ++rc)
                rowaddr[rc] = abase + (mbase + 8 * rc + g) * 128;

            #pragma unroll
            for (int q = 0; q < 2; ++q) {
                const int cq = ((q * 4 + t) ^ chunkxor) * 16;
                uint32_t A[4][4];
                #pragma unroll
                for (int rc = 0; rc < 4; ++rc) {
                    uint32_t r0, r1, r2, r3;
                    asm volatile("ld.shared.v4.b32 {%0,%1,%2,%3}, [%4];"
                                 : "=r"(r0), "=r"(r1), "=r"(r2), "=r"(r3)
                                 : "r"(rowaddr[rc] + cq));
                    A[rc][0] = f2tf32(__uint_as_float(r0));
                    A[rc][1] = f2tf32(__uint_as_float(r1));
                    A[rc][2] = f2tf32(__uint_as_float(r2));
                    A[rc][3] = f2tf32(__uint_as_float(r3));
                }
                #pragma unroll
                for (int nt = 0; nt < 4; ++nt) {
                    const int ntp = chalf * 4 + nt;
                    uint32_t b0, b1, b2, b3;
                    uint32_t baddr = shb + OFF_B * 4
                                   + ((ntp * 4 + h * 2 + q) * 32 + lid) * 16;
                    asm volatile("ld.shared.v4.b32 {%0,%1,%2,%3}, [%4];"
                                 : "=r"(b0), "=r"(b1), "=r"(b2), "=r"(b3)
                                 : "r"(baddr));
                    // k-step sl = 2q (s'=0): elements 0,1 of each A row / b0,b1
                    mma_tf32(acc[0][nt], A[0][0], A[1][0], A[0][1], A[1][1], b0, b1);
                    mma_tf32(acc[1][nt], A[2][0], A[3][0], A[2][1], A[3][1], b0, b1);
                    // k-step sl = 2q+1 (s'=1): elements 2,3 / b2,b3
                    mma_tf32(acc[0][nt], A[0][2], A[1][2], A[0][3], A[1][3], b2, b3);
                    mma_tf32(acc[1][nt], A[2][2], A[3][2], A[2][3], A[3][3], b2, b3);
                }
            }
        }

        if (h == 1) {
            // ---- Scatter: v4 global reductions, 4 contiguous couts each ----
            const int slot = li % 3;
            #pragma unroll
            for (int mt = 0; mt < 2; ++mt) {
                #pragma unroll
                for (int half = 0; half < 2; ++half) {
                    int ml = mbase + mt * 16 + g + half * 8;
                    int m = m0 + ml;
                    if (m < MPAIRS) {
                        int orow = (int)sh[OFF_OMAP + slot * TILE_M + ml];
                        float* dst = out + (size_t)orow * COUT + t * 4;
                        #pragma unroll
                        for (int pp = 0; pp < 2; ++pp) {
                            int P = chalf * 2 + pp;
                            asm volatile("red.global.add.v4.f32 [%0], {%1,%2,%3,%4};"
                                         :: "l"(dst + 16 * P),
                                            "f"(acc[mt][2 * pp][half * 2]),
                                            "f"(acc[mt][2 * pp][half * 2 + 1]),
                                            "f"(acc[mt][2 * pp + 1][half * 2]),
                                            "f"(acc[mt][2 * pp + 1][half * 2 + 1]) : "memory");
                        }
                    }
                }
            }
        }
    }
}

extern "C" void kernel_launch(void* const* d_in, const int* in_sizes, int n_in,
                              void* d_out, int out_size) {
    const float* feats   = (const float*)d_in[0];   // [N, 64]
    const float* kern    = (const float*)d_in[1];   // [27, 64, 64]
    const int*   in_map  = (const int*)d_in[2];     // [27, 50000]
    const int*   out_map = (const int*)d_in[3];     // [27, 50000]
    float* out = (float*)d_out;                     // [N, 64]

    int n4 = NVOX * COUT / 4;
    spconv_zero_kernel<<<(n4 + 255) / 256, 256>>>((float4*)out, n4);

    int smem_bytes = SMEM_WORDS * (int)sizeof(uint32_t);   // 52224 B -> 4 CTAs/SM
    cudaFuncSetAttribute(spconv_pers_kernel,
                         cudaFuncAttributeMaxDynamicSharedMemorySize, smem_bytes);
    spconv_pers_kernel<<<NCTA, NTHREADS, smem_bytes>>>(feats, kern, in_map, out_map, out);
}

// round 15
// speedup vs baseline: 1.7123x; 1.7123x over previous
#include <cuda_runtime.h>
#include <cuda_fp16.h>
#include <cstdint>

// Sparse 3D conv, persistent-CTA pipelined, fp16 tensor path (m16n8k16 mma;
// tcgen05 PTX rejected by harness's compute_103 target).
// out[out_map[k,m]] += feats[in_map[k,m]] @ kernel[k]
// N=200000, K=27, M=50000, Cin=Cout=64, fp32 in/out, fp16(RN) operands.
//
// R14 = R12 pipeline skeleton (pair-decoupled, half-tile double buffer,
// 4 CTAs/SM) with: feats pre-converted once to a fragment-permuted fp16
// __device__ array (halves the 27x gather traffic), fp16 B tile, and
// m16n8k16 mma (half the mma count, zero cvts in the hot loop).

#define KOFF    27
#define MPAIRS  50000
#define NVOX    200000
#define CIN     64
#define COUT    64
#define TILE_M  128
#define NTHREADS 256
#define TPK     391                 // ceil(50000/128)
#define NCTA    608                 // 4 per SM
#define QT      17                  // 27*391 = 10557 = 608*17 + 221
#define RT      221

#define AB_STRIDE   96                          // bytes per 32-fp16 row (pad for banks)
#define ABUF_BYTES  (TILE_M * AB_STRIDE)        // 12288 per buffer
#define OFFB_B      (2 * ABUF_BYTES)            // 24576: fp16 fragment-packed W^T (8 KB)
#define IDX_W       8192                        // word index of IDX[3][128]
#define OMAP_W      (IDX_W + 3 * TILE_M)        // 8576
#define SMEM_BYTES  ((OMAP_W + 3 * TILE_M) * 4) // 35840

// Pre-permuted fp16 copy of feats (fragment order within each 16-cin window).
__device__ __half g_feats16[(size_t)NVOX * CIN];

__device__ __forceinline__ void cp16(uint32_t dst, const void* src) {
    asm volatile("cp.async.cg.shared.global [%0], [%1], 16;" :: "r"(dst), "l"(src));
}
__device__ __forceinline__ void pair_bar(int id) {
    asm volatile("bar.sync %0, 64;" :: "r"(id) : "memory");
}
__device__ __forceinline__ void mma16(float c[4], uint32_t a0, uint32_t a1,
                                      uint32_t a2, uint32_t a3,
                                      uint32_t b0, uint32_t b1) {
    asm volatile(
        "mma.sync.aligned.m16n8k16.row.col.f32.f16.f16.f32 "
        "{%0,%1,%2,%3}, {%4,%5,%6,%7}, {%8,%9}, {%0,%1,%2,%3};"
        : "+f"(c[0]), "+f"(c[1]), "+f"(c[2]), "+f"(c[3])
        : "r"(a0), "r"(a1), "r"(a2), "r"(a3), "r"(b0), "r"(b1));
}

__global__ void spconv_zero_kernel(float4* __restrict__ out, int n4) {
    int i = blockIdx.x * blockDim.x + threadIdx.x;
    if (i < n4) out[i] = make_float4(0.f, 0.f, 0.f, 0.f);
}

// feats fp32 -> permuted fp16. Perm: cin c -> p = (c & ~15) | (4*((j>>1)&3)
// + 2*(j>>3) + (j&1)) with j = c&15, so thread(g,t)'s mma fragment slots
// {2t,2t+1,2t+8,2t+9} become 4 contiguous halfs.
__global__ void spconv_cvt_kernel(const float* __restrict__ feats) {
    int idx = blockIdx.x * blockDim.x + threadIdx.x;
    if (idx < NVOX * CIN) {
        int r = idx >> 6, c = idx & 63;
        int j = c & 15;
        int p = (c & ~15) | (((j >> 1) & 3) * 4 + ((j >> 3) << 1) + (j & 1));
        g_feats16[((size_t)r << 6) + p] = __float2half(feats[idx]);
    }
}

__global__ __launch_bounds__(NTHREADS, 4)
void spconv_pers_kernel(const float* __restrict__ kern,
                        const int*   __restrict__ in_map,
                        const int*   __restrict__ out_map,
                        float*       __restrict__ out)
{
    extern __shared__ uint32_t sh[];
    const uint32_t shb = (uint32_t)__cvta_generic_to_shared(sh);

    const int tid = threadIdx.x;
    const int wid = tid >> 5;
    const int lid = tid & 31;
    const int cta = blockIdx.x;

    const int t0  = cta * QT + (cta < RT ? cta : RT);
    const int cnt = QT + (cta < RT ? 1 : 0);
    const int S   = cnt * 2;

    const int g = lid >> 2, t = lid & 3;
    const int rgrpw = wid >> 1, chalf = wid & 1;
    const int mbase = rgrpw * 32;              // pair's 32-row segment
    const int pt    = tid & 63;
    const int barid = rgrpw + 1;

    // ---- Prologue: each pair fetches its idx/omap segment of tile t0 ----
    {
        int k0 = t0 / TPK, m00 = (t0 % TPK) * TILE_M;
        if (pt < 8) {
            int m = m00 + mbase + pt * 4;
            if (m < MPAIRS)
                cp16(shb + (IDX_W + mbase + pt * 4) * 4,
                     in_map + (size_t)k0 * MPAIRS + m);
        } else if (pt < 16) {
            int ci = pt - 8;
            int m = m00 + mbase + ci * 4;
            if (m < MPAIRS)
                cp16(shb + (OMAP_W + mbase + ci * 4) * 4,
                     out_map + (size_t)k0 * MPAIRS + m);
        }
        asm volatile("cp.async.commit_group;" ::: "memory");
        asm volatile("cp.async.wait_group 0;" ::: "memory");
        pair_bar(barid);
    }

    // Pair-private gather: 32 rows x 64B (half h of the fp16 row) per stage.
    auto issue_stage = [&](int sp) {
        int li = sp >> 1, h = sp & 1;
        int tt = t0 + li;
        int m0 = (tt % TPK) * TILE_M;
        int slot = li % 3;
        uint32_t abase = shb + (sp & 1) * ABUF_BYTES;
        #pragma unroll
        for (int j = 0; j < 2; ++j) {
            int cch = pt + j * 64;             // 0..127 = 32 rows x 4 chunks
            int rl = cch >> 2, ch = cch & 3;
            int row = mbase + rl;
            int m = m0 + row;
            int gi = (int)sh[IDX_W + slot * TILE_M + row];
            int srow = (m < MPAIRS) ? gi : 0;
            cp16(abase + row * AB_STRIDE + ch * 16,
                 (const char*)g_feats16 + (size_t)srow * 128 + h * 64 + ch * 16);
        }
        if (h == 0 && li + 1 < cnt) {
            int tt2 = tt + 1;
            int k2 = tt2 / TPK, m02 = (tt2 % TPK) * TILE_M;
            int slot2 = (li + 1) % 3;
            if (pt < 8) {
                int m = m02 + mbase + pt * 4;
                if (m < MPAIRS)
                    cp16(shb + (IDX_W + slot2 * TILE_M + mbase + pt * 4) * 4,
                         in_map + (size_t)k2 * MPAIRS + m);
            } else if (pt < 16) {
                int ci = pt - 8;
                int m = m02 + mbase + ci * 4;
                if (m < MPAIRS)
                    cp16(shb + (OMAP_W + slot2 * TILE_M + mbase + ci * 4) * 4,
                         out_map + (size_t)k2 * MPAIRS + m);
            }
        }
        asm volatile("cp.async.commit_group;" ::: "memory");
    };

    issue_stage(0);

    float acc[2][4][4];
    int cur_k = -1;

    for (int s = 0; s < S; ++s) {
        asm volatile("cp.async.wait_group 0;" ::: "memory");
        pair_bar(barid);

        const int li = s >> 1, h = s & 1;
        const int tt = t0 + li;
        const int kk = tt / TPK;
        const int m0 = (tt % TPK) * TILE_M;

        if (h == 0) {
            if (kk != cur_k) {
                // ---- Rare CTA-wide B restage (fp16 fragment packing) ----
                __syncthreads();
                const float* W = kern + (size_t)kk * CIN * COUT;
                #pragma unroll
                for (int idx = tid; idx < CIN * COUT; idx += NTHREADS) {
                    int i = idx >> 6;              // cin
                    int o = idx & 63;              // cout
                    int P = o >> 4, local = o & 15;
                    int ttq = local >> 2, rr = local & 3;
                    int pos = (2 * P + (rr >> 1)) * 8 + 2 * ttq + (rr & 1);
                    int nt = pos >> 3, gg = pos & 7;
                    int sg = i >> 4, j = i & 15;
                    int tj = (j >> 1) & 3, e = j & 1, d = j >> 3;
                    uint32_t off = OFFB_B + (((nt * 4 + sg) * 32) + gg * 4 + tj) * 8
                                 + d * 4 + e * 2;
                    *(__half*)((char*)sh + off) = __float2half(W[idx]);
                }
                cur_k = kk;
                __syncthreads();
            }
            #pragma unroll
            for (int mt = 0; mt < 2; ++mt)
                #pragma unroll
                for (int nt = 0; nt < 4; ++nt)
                    #pragma unroll
                    for (int e = 0; e < 4; ++e) acc[mt][nt][e] = 0.f;
        }

        if (s + 1 < S) issue_stage(s + 1);

        // ---- GEMM: 2 k16-steps per half-tile, fp16 fragments ----
        {
            uint32_t abase = shb + (s & 1) * ABUF_BYTES;
            #pragma unroll
            for (int sgl = 0; sgl < 2; ++sgl) {
                const int sg = h * 2 + sgl;
                uint32_t a[2][4];
                #pragma unroll
                for (int mt = 0; mt < 2; ++mt) {
                    uint32_t addr = abase + (mbase + mt * 16 + g) * AB_STRIDE
                                  + sgl * 32 + t * 8;
                    asm volatile("ld.shared.v2.b32 {%0,%1}, [%2];"
                                 : "=r"(a[mt][0]), "=r"(a[mt][2]) : "r"(addr));
                    asm volatile("ld.shared.v2.b32 {%0,%1}, [%2];"
                                 : "=r"(a[mt][1]), "=r"(a[mt][3])
                                 : "r"(addr + 8 * AB_STRIDE));
                }
                #pragma unroll
                for (int nt = 0; nt < 4; ++nt) {
                    const int ntp = chalf * 4 + nt;
                    uint32_t b0, b1;
                    uint32_t baddr = shb + OFFB_B + ((ntp * 4 + sg) * 32 + lid) * 8;
                    asm volatile("ld.shared.v2.b32 {%0,%1}, [%2];"
                                 : "=r"(b0), "=r"(b1) : "r"(baddr));
                    mma16(acc[0][nt], a[0][0], a[0][1], a[0][2], a[0][3], b0, b1);
                    mma16(acc[1][nt], a[1][0], a[1][1], a[1][2], a[1][3], b0, b1);
                }
            }
        }

        if (h == 1) {
            // ---- Scatter: v4 global reductions, 4 contiguous couts each ----
            const int slot = li % 3;
            #pragma unroll
            for (int mt = 0; mt < 2; ++mt) {
                #pragma unroll
                for (int half = 0; half < 2; ++half) {
                    int ml = mbase + mt * 16 + g + half * 8;
                    int m = m0 + ml;
                    if (m < MPAIRS) {
                        int orow = (int)sh[OMAP_W + slot * TILE_M + ml];
                        float* dst = out + (size_t)orow * COUT + t * 4;
                        #pragma unroll
                        for (int pp = 0; pp < 2; ++pp) {
                            int P = chalf * 2 + pp;
                            asm volatile("red.global.add.v4.f32 [%0], {%1,%2,%3,%4};"
                                         :: "l"(dst + 16 * P),
                                            "f"(acc[mt][2 * pp][half * 2]),
                                            "f"(acc[mt][2 * pp][half * 2 + 1]),
                                            "f"(acc[mt][2 * pp + 1][half * 2]),
                                            "f"(acc[mt][2 * pp + 1][half * 2 + 1]) : "memory");
                        }
                    }
                }
            }
        }
    }
}

extern "C" void kernel_launch(void* const* d_in, const int* in_sizes, int n_in,
                              void* d_out, int out_size) {
    const float* feats   = (const float*)d_in[0];   // [N, 64]
    const float* kern    = (const float*)d_in[1];   // [27, 64, 64]
    const int*   in_map  = (const int*)d_in[2];     // [27, 50000]
    const int*   out_map = (const int*)d_in[3];     // [27, 50000]
    float* out = (float*)d_out;                     // [N, 64]

    int n4 = NVOX * COUT / 4;
    spconv_zero_kernel<<<(n4 + 255) / 256, 256>>>((float4*)out, n4);

    int ncvt = (NVOX * CIN + 255) / 256;
    spconv_cvt_kernel<<<ncvt, 256>>>(feats);

    cudaFuncSetAttribute(spconv_pers_kernel,
                         cudaFuncAttributeMaxDynamicSharedMemorySize, SMEM_BYTES);
    spconv_pers_kernel<<<NCTA, NTHREADS, SMEM_BYTES>>>(kern, in_map, out_map, out);
}

// round 16
// speedup vs baseline: 2.1122x; 1.2335x over previous
#include <cuda_runtime.h>
#include <cuda_fp16.h>
#include <cstdint>

// Sparse 3D conv, persistent-CTA 3-deep pipelined fp16 tensor path (m16n8k16;
// tcgen05 PTX rejected by harness's compute_103 target).
// out[out_map[k,m]] += feats[in_map[k,m]] @ kernel[k]
// N=200000, K=27, M=50000, Cin=Cout=64, fp32 in/out, fp16(RN) operands.
//
// R15 = R14 + fused zero/cvt prologue kernel + third A buffer (gather gets two
// compute phases of latency cover; wait_group 1 steady state).

#define KOFF    27
#define MPAIRS  50000
#define NVOX    200000
#define CIN     64
#define COUT    64
#define TILE_M  128
#define NTHREADS 256
#define TPK     391                 // ceil(50000/128)
#define NCTA    608                 // 4 per SM
#define QT      17                  // 27*391 = 10557 = 608*17 + 221
#define RT      221

#define AB_STRIDE   96                          // bytes per 32-fp16 row (pad for banks)
#define ABUF_BYTES  (TILE_M * AB_STRIDE)        // 12288 per buffer
#define OFFB_B      (3 * ABUF_BYTES)            // 36864: fp16 fragment-packed W^T (8 KB)
#define IDX_W       11264                       // word index of IDX[3][128]
#define OMAP_W      (IDX_W + 3 * TILE_M)        // 11648
#define SMEM_BYTES  ((OMAP_W + 3 * TILE_M) * 4) // 48128 -> 4 CTAs/SM

// Pre-permuted fp16 copy of feats (fragment order within each 16-cin window).
__device__ __half g_feats16[(size_t)NVOX * CIN];

__device__ __forceinline__ void cp16(uint32_t dst, const void* src) {
    asm volatile("cp.async.cg.shared.global [%0], [%1], 16;" :: "r"(dst), "l"(src));
}
__device__ __forceinline__ void pair_bar(int id) {
    asm volatile("bar.sync %0, 64;" :: "r"(id) : "memory");
}
__device__ __forceinline__ void mma16(float c[4], uint32_t a0, uint32_t a1,
                                      uint32_t a2, uint32_t a3,
                                      uint32_t b0, uint32_t b1) {
    asm volatile(
        "mma.sync.aligned.m16n8k16.row.col.f32.f16.f16.f32 "
        "{%0,%1,%2,%3}, {%4,%5,%6,%7}, {%8,%9}, {%0,%1,%2,%3};"
        : "+f"(c[0]), "+f"(c[1]), "+f"(c[2]), "+f"(c[3])
        : "r"(a0), "r"(a1), "r"(a2), "r"(a3), "r"(b0), "r"(b1));
}

// Fused: zero d_out (3.2M float4) AND convert feats fp32 -> permuted fp16
// (3.2M float4 reads; same index range). Perm per 16-cin window j = c&15:
// p = (c&~15) | (4*((j>>1)&3) + 2*(j>>3) + (j&1)) -> float4 at c4 lands as two
// half2 words at p0 and p0+4.
__global__ void spconv_init_kernel(const float* __restrict__ feats,
                                   float4* __restrict__ out) {
    int i = blockIdx.x * blockDim.x + threadIdx.x;
    if (i < NVOX * COUT / 4)
        out[i] = make_float4(0.f, 0.f, 0.f, 0.f);
    if (i < NVOX * CIN / 4) {
        float4 v = reinterpret_cast<const float4*>(feats)[i];
        int r  = i >> 4;                 // row (16 float4 per 64-col row)
        int c4 = (i & 15) * 4;           // starting cin
        int a  = (c4 >> 2) & 3;
        int p0 = ((2 * a) & 3) * 4 + ((a >> 1) << 1);   // within 16-window
        __half2* dst = reinterpret_cast<__half2*>(
            g_feats16 + ((size_t)r << 6) + (c4 & ~15) + p0);
        dst[0] = __floats2half2_rn(v.x, v.y);
        dst[2] = __floats2half2_rn(v.z, v.w);   // p0+4 halfs = +2 half2
    }
}

__global__ __launch_bounds__(NTHREADS, 4)
void spconv_pers_kernel(const float* __restrict__ kern,
                        const int*   __restrict__ in_map,
                        const int*   __restrict__ out_map,
                        float*       __restrict__ out)
{
    extern __shared__ uint32_t sh[];
    const uint32_t shb = (uint32_t)__cvta_generic_to_shared(sh);

    const int tid = threadIdx.x;
    const int wid = tid >> 5;
    const int lid = tid & 31;
    const int cta = blockIdx.x;

    const int t0  = cta * QT + (cta < RT ? cta : RT);
    const int cnt = QT + (cta < RT ? 1 : 0);
    const int S   = cnt * 2;

    const int g = lid >> 2, t = lid & 3;
    const int rgrpw = wid >> 1, chalf = wid & 1;
    const int mbase = rgrpw * 32;              // pair's 32-row segment
    const int pt    = tid & 63;
    const int barid = rgrpw + 1;

    // ---- Prologue: each pair fetches its idx/omap segment of tile t0 ----
    {
        int k0 = t0 / TPK, m00 = (t0 % TPK) * TILE_M;
        if (pt < 8) {
            int m = m00 + mbase + pt * 4;
            if (m < MPAIRS)
                cp16(shb + (IDX_W + mbase + pt * 4) * 4,
                     in_map + (size_t)k0 * MPAIRS + m);
        } else if (pt < 16) {
            int ci = pt - 8;
            int m = m00 + mbase + ci * 4;
            if (m < MPAIRS)
                cp16(shb + (OMAP_W + mbase + ci * 4) * 4,
                     out_map + (size_t)k0 * MPAIRS + m);
        }
        asm volatile("cp.async.commit_group;" ::: "memory");
        asm volatile("cp.async.wait_group 0;" ::: "memory");
        pair_bar(barid);
    }

    // Pair-private gather into buffer buf (=sp%3): 32 rows x 64B (half h).
    auto issue_stage = [&](int sp, int buf) {
        int li = sp >> 1, h = sp & 1;
        int tt = t0 + li;
        int m0 = (tt % TPK) * TILE_M;
        int slot = li % 3;
        uint32_t abase = shb + buf * ABUF_BYTES;
        #pragma unroll
        for (int j = 0; j < 2; ++j) {
            int cch = pt + j * 64;             // 0..127 = 32 rows x 4 chunks
            int rl = cch >> 2, ch = cch & 3;
            int row = mbase + rl;
            int m = m0 + row;
            int gi = (int)sh[IDX_W + slot * TILE_M + row];
            int srow = (m < MPAIRS) ? gi : 0;
            cp16(abase + row * AB_STRIDE + ch * 16,
                 (const char*)g_feats16 + (size_t)srow * 128 + h * 64 + ch * 16);
        }
        if (h == 0 && li + 1 < cnt) {
            int tt2 = tt + 1;
            int k2 = tt2 / TPK, m02 = (tt2 % TPK) * TILE_M;
            int slot2 = (li + 1) % 3;
            if (pt < 8) {
                int m = m02 + mbase + pt * 4;
                if (m < MPAIRS)
                    cp16(shb + (IDX_W + slot2 * TILE_M + mbase + pt * 4) * 4,
                         in_map + (size_t)k2 * MPAIRS + m);
            } else if (pt < 16) {
                int ci = pt - 8;
                int m = m02 + mbase + ci * 4;
                if (m < MPAIRS)
                    cp16(shb + (OMAP_W + slot2 * TILE_M + mbase + ci * 4) * 4,
                         out_map + (size_t)k2 * MPAIRS + m);
            }
        }
        asm volatile("cp.async.commit_group;" ::: "memory");
    };

    issue_stage(0, 0);
    if (S > 1) issue_stage(1, 1);

    float acc[2][4][4];
    int cur_k = -1;
    int buf = 0;                               // = s % 3

    for (int s = 0; s < S; ++s) {
        // Outstanding: groups s, s+1 (if exists). Retire s; keep s+1 in flight.
        if (s + 1 < S) {
            asm volatile("cp.async.wait_group 1;" ::: "memory");
        } else {
            asm volatile("cp.async.wait_group 0;" ::: "memory");
        }
        pair_bar(barid);

        int buf2 = buf + 2; if (buf2 >= 3) buf2 -= 3;
        if (s + 2 < S) issue_stage(s + 2, buf2);

        const int li = s >> 1, h = s & 1;
        const int tt = t0 + li;
        const int kk = tt / TPK;
        const int m0 = (tt % TPK) * TILE_M;

        if (h == 0) {
            if (kk != cur_k) {
                // ---- Rare CTA-wide B restage (fp16 fragment packing) ----
                __syncthreads();
                const float* W = kern + (size_t)kk * CIN * COUT;
                #pragma unroll
                for (int idx = tid; idx < CIN * COUT; idx += NTHREADS) {
                    int i = idx >> 6;              // cin
                    int o = idx & 63;              // cout
                    int P = o >> 4, local = o & 15;
                    int ttq = local >> 2, rr = local & 3;
                    int pos = (2 * P + (rr >> 1)) * 8 + 2 * ttq + (rr & 1);
                    int nt = pos >> 3, gg = pos & 7;
                    int sg = i >> 4, j = i & 15;
                    int tj = (j >> 1) & 3, e = j & 1, d = j >> 3;
                    uint32_t off = OFFB_B + (((nt * 4 + sg) * 32) + gg * 4 + tj) * 8
                                 + d * 4 + e * 2;
                    *(__half*)((char*)sh + off) = __float2half(W[idx]);
                }
                cur_k = kk;
                __syncthreads();
            }
            #pragma unroll
            for (int mt = 0; mt < 2; ++mt)
                #pragma unroll
                for (int nt = 0; nt < 4; ++nt)
                    #pragma unroll
                    for (int e = 0; e < 4; ++e) acc[mt][nt][e] = 0.f;
        }

        // ---- GEMM: 2 k16-steps per half-tile, fp16 fragments ----
        {
            uint32_t abase = shb + buf * ABUF_BYTES;
            #pragma unroll
            for (int sgl = 0; sgl < 2; ++sgl) {
                const int sg = h * 2 + sgl;
                uint32_t a[2][4];
                #pragma unroll
                for (int mt = 0; mt < 2; ++mt) {
                    uint32_t addr = abase + (mbase + mt * 16 + g) * AB_STRIDE
                                  + sgl * 32 + t * 8;
                    asm volatile("ld.shared.v2.b32 {%0,%1}, [%2];"
                                 : "=r"(a[mt][0]), "=r"(a[mt][2]) : "r"(addr));
                    asm volatile("ld.shared.v2.b32 {%0,%1}, [%2];"
                                 : "=r"(a[mt][1]), "=r"(a[mt][3])
                                 : "r"(addr + 8 * AB_STRIDE));
                }
                #pragma unroll
                for (int nt = 0; nt < 4; ++nt) {
                    const int ntp = chalf * 4 + nt;
                    uint32_t b0, b1;
                    uint32_t baddr = shb + OFFB_B + ((ntp * 4 + sg) * 32 + lid) * 8;
                    asm volatile("ld.shared.v2.b32 {%0,%1}, [%2];"
                                 : "=r"(b0), "=r"(b1) : "r"(baddr));
                    mma16(acc[0][nt], a[0][0], a[0][1], a[0][2], a[0][3], b0, b1);
                    mma16(acc[1][nt], a[1][0], a[1][1], a[1][2], a[1][3], b0, b1);
                }
            }
        }

        if (h == 1) {
            // ---- Scatter: v4 global reductions, 4 contiguous couts each ----
            const int slot = li % 3;
            #pragma unroll
            for (int mt = 0; mt < 2; ++mt) {
                #pragma unroll
                for (int half = 0; half < 2; ++half) {
                    int ml = mbase + mt * 16 + g + half * 8;
                    int m = m0 + ml;
                    if (m < MPAIRS) {
                        int orow = (int)sh[OMAP_W + slot * TILE_M + ml];
                        float* dst = out + (size_t)orow * COUT + t * 4;
                        #pragma unroll
                        for (int pp = 0; pp < 2; ++pp) {
                            int P = chalf * 2 + pp;
                            asm volatile("red.global.add.v4.f32 [%0], {%1,%2,%3,%4};"
                                         :: "l"(dst + 16 * P),
                                            "f"(acc[mt][2 * pp][half * 2]),
                                            "f"(acc[mt][2 * pp][half * 2 + 1]),
                                            "f"(acc[mt][2 * pp + 1][half * 2]),
                                            "f"(acc[mt][2 * pp + 1][half * 2 + 1]) : "memory");
                        }
                    }
                }
            }
        }

        if (++buf == 3) buf = 0;
    }
}

extern "C" void kernel_launch(void* const* d_in, const int* in_sizes, int n_in,
                              void* d_out, int out_size) {
    const float* feats   = (const float*)d_in[0];   // [N, 64]
    const float* kern    = (const float*)d_in[1];   // [27, 64, 64]
    const int*   in_map  = (const int*)d_in[2];     // [27, 50000]
    const int*   out_map = (const int*)d_in[3];     // [27, 50000]
    float* out = (float*)d_out;                     // [N, 64]

    // Fused zero + fp32->fp16 permuted convert (same 3.2M-float4 index range).
    int n4 = NVOX * COUT / 4;
    spconv_init_kernel<<<(n4 + 255) / 256, 256>>>(feats, (float4*)out);

    cudaFuncSetAttribute(spconv_pers_kernel,
                         cudaFuncAttributeMaxDynamicSharedMemorySize, SMEM_BYTES);
    spconv_pers_kernel<<<NCTA, NTHREADS, SMEM_BYTES>>>(kern, in_map, out_map, out);
}

// round 17
// speedup vs baseline: 2.1542x; 1.0199x over previous
#include <cuda_runtime.h>
#include <cuda_fp16.h>
#include <cstdint>

// Sparse 3D conv, persistent-CTA 3-deep pipelined fp16 tensor path (m16n8k16;
// tcgen05 PTX rejected by harness's compute_103 target).
// out[out_map[k,m]] += feats[in_map[k,m]] @ kernel[k]
// N=200000, K=27, M=50000, Cin=Cout=64, fp32 in/out, fp16(RN) operands.
//
// R16 = R15 + XOR-chunk A smem layout at 64B stride: chunk ch of row r lands
// at ch^(r&3), making BOTH the cp.async store phase pattern and the LDS.64
// fragment loads bank-conflict-free (the 96B-stride layout 2-way conflicted
// every A load: 24g mod 32 collides for g and g+4).

#define KOFF    27
#define MPAIRS  50000
#define NVOX    200000
#define CIN     64
#define COUT    64
#define TILE_M  128
#define NTHREADS 256
#define TPK     391                 // ceil(50000/128)
#define NCTA    608                 // 4 per SM
#define QT      17                  // 27*391 = 10557 = 608*17 + 221
#define RT      221

#define AB_STRIDE   64                          // bytes per 32-fp16 row (XOR swizzled)
#define ABUF_BYTES  (TILE_M * AB_STRIDE)        // 8192 per buffer
#define OFFB_B      (3 * ABUF_BYTES)            // 24576: fp16 fragment-packed W^T (8 KB)
#define IDX_W       8192                        // word index of IDX[3][128]
#define OMAP_W      (IDX_W + 3 * TILE_M)        // 8576
#define SMEM_BYTES  ((OMAP_W + 3 * TILE_M) * 4) // 35840 -> 4 CTAs/SM

// Pre-permuted fp16 copy of feats (fragment order within each 16-cin window).
__device__ __half g_feats16[(size_t)NVOX * CIN];

__device__ __forceinline__ void cp16(uint32_t dst, const void* src) {
    asm volatile("cp.async.cg.shared.global [%0], [%1], 16;" :: "r"(dst), "l"(src));
}
__device__ __forceinline__ void pair_bar(int id) {
    asm volatile("bar.sync %0, 64;" :: "r"(id) : "memory");
}
__device__ __forceinline__ void mma16(float c[4], uint32_t a0, uint32_t a1,
                                      uint32_t a2, uint32_t a3,
                                      uint32_t b0, uint32_t b1) {
    asm volatile(
        "mma.sync.aligned.m16n8k16.row.col.f32.f16.f16.f32 "
        "{%0,%1,%2,%3}, {%4,%5,%6,%7}, {%8,%9}, {%0,%1,%2,%3};"
        : "+f"(c[0]), "+f"(c[1]), "+f"(c[2]), "+f"(c[3])
        : "r"(a0), "r"(a1), "r"(a2), "r"(a3), "r"(b0), "r"(b1));
}

// Fused: zero d_out (3.2M float4) AND convert feats fp32 -> permuted fp16
// (same index range). Perm per 16-cin window j = c&15:
// p = (c&~15) | (4*((j>>1)&3) + 2*(j>>3) + (j&1)).
__global__ void spconv_init_kernel(const float* __restrict__ feats,
                                   float4* __restrict__ out) {
    int i = blockIdx.x * blockDim.x + threadIdx.x;
    if (i < NVOX * COUT / 4)
        out[i] = make_float4(0.f, 0.f, 0.f, 0.f);
    if (i < NVOX * CIN / 4) {
        float4 v = reinterpret_cast<const float4*>(feats)[i];
        int r  = i >> 4;                 // row (16 float4 per 64-col row)
        int c4 = (i & 15) * 4;           // starting cin
        int a  = (c4 >> 2) & 3;
        int p0 = ((2 * a) & 3) * 4 + ((a >> 1) << 1);   // within 16-window
        __half2* dst = reinterpret_cast<__half2*>(
            g_feats16 + ((size_t)r << 6) + (c4 & ~15) + p0);
        dst[0] = __floats2half2_rn(v.x, v.y);
        dst[2] = __floats2half2_rn(v.z, v.w);   // p0+4 halfs = +2 half2
    }
}

__global__ __launch_bounds__(NTHREADS, 4)
void spconv_pers_kernel(const float* __restrict__ kern,
                        const int*   __restrict__ in_map,
                        const int*   __restrict__ out_map,
                        float*       __restrict__ out)
{
    extern __shared__ uint32_t sh[];
    const uint32_t shb = (uint32_t)__cvta_generic_to_shared(sh);

    const int tid = threadIdx.x;
    const int wid = tid >> 5;
    const int lid = tid & 31;
    const int cta = blockIdx.x;

    const int t0  = cta * QT + (cta < RT ? cta : RT);
    const int cnt = QT + (cta < RT ? 1 : 0);
    const int S   = cnt * 2;

    const int g = lid >> 2, t = lid & 3;
    const int rgrpw = wid >> 1, chalf = wid & 1;
    const int mbase = rgrpw * 32;              // pair's 32-row segment
    const int pt    = tid & 63;
    const int barid = rgrpw + 1;

    // ---- Prologue: each pair fetches its idx/omap segment of tile t0 ----
    {
        int k0 = t0 / TPK, m00 = (t0 % TPK) * TILE_M;
        if (pt < 8) {
            int m = m00 + mbase + pt * 4;
            if (m < MPAIRS)
                cp16(shb + (IDX_W + mbase + pt * 4) * 4,
                     in_map + (size_t)k0 * MPAIRS + m);
        } else if (pt < 16) {
            int ci = pt - 8;
            int m = m00 + mbase + ci * 4;
            if (m < MPAIRS)
                cp16(shb + (OMAP_W + mbase + ci * 4) * 4,
                     out_map + (size_t)k0 * MPAIRS + m);
        }
        asm volatile("cp.async.commit_group;" ::: "memory");
        asm volatile("cp.async.wait_group 0;" ::: "memory");
        pair_bar(barid);
    }

    // Pair-private gather into buffer buf (=sp%3): 32 rows x 64B (half h),
    // chunk ch stored XOR-swizzled at ch^(row&3).
    auto issue_stage = [&](int sp, int buf) {
        int li = sp >> 1, h = sp & 1;
        int tt = t0 + li;
        int m0 = (tt % TPK) * TILE_M;
        int slot = li % 3;
        uint32_t abase = shb + buf * ABUF_BYTES;
        #pragma unroll
        for (int j = 0; j < 2; ++j) {
            int cch = pt + j * 64;             // 0..127 = 32 rows x 4 chunks
            int rl = cch >> 2, ch = cch & 3;
            int row = mbase + rl;
            int m = m0 + row;
            int gi = (int)sh[IDX_W + slot * TILE_M + row];
            int srow = (m < MPAIRS) ? gi : 0;
            int chs = ch ^ (row & 3);          // conflict-free swizzle
            cp16(abase + row * AB_STRIDE + chs * 16,
                 (const char*)g_feats16 + (size_t)srow * 128 + h * 64 + ch * 16);
        }
        if (h == 0 && li + 1 < cnt) {
            int tt2 = tt + 1;
            int k2 = tt2 / TPK, m02 = (tt2 % TPK) * TILE_M;
            int slot2 = (li + 1) % 3;
            if (pt < 8) {
                int m = m02 + mbase + pt * 4;
                if (m < MPAIRS)
                    cp16(shb + (IDX_W + slot2 * TILE_M + mbase + pt * 4) * 4,
                         in_map + (size_t)k2 * MPAIRS + m);
            } else if (pt < 16) {
                int ci = pt - 8;
                int m = m02 + mbase + ci * 4;
                if (m < MPAIRS)
                    cp16(shb + (OMAP_W + slot2 * TILE_M + mbase + ci * 4) * 4,
                         out_map + (size_t)k2 * MPAIRS + m);
            }
        }
        asm volatile("cp.async.commit_group;" ::: "memory");
    };

    issue_stage(0, 0);
    if (S > 1) issue_stage(1, 1);

    float acc[2][4][4];
    int cur_k = -1;
    int buf = 0;                               // = s % 3
    const int gx = g & 3;                      // XOR key for A loads
    const int tsub = (t >> 1);                 // logical chunk sub-index
    const int toff = (t & 1) * 8;              // byte offset within chunk

    for (int s = 0; s < S; ++s) {
        if (s + 1 < S) {
            asm volatile("cp.async.wait_group 1;" ::: "memory");
        } else {
            asm volatile("cp.async.wait_group 0;" ::: "memory");
        }
        pair_bar(barid);

        int buf2 = buf + 2; if (buf2 >= 3) buf2 -= 3;
        if (s + 2 < S) issue_stage(s + 2, buf2);

        const int li = s >> 1, h = s & 1;
        const int tt = t0 + li;
        const int kk = tt / TPK;
        const int m0 = (tt % TPK) * TILE_M;

        if (h == 0) {
            if (kk != cur_k) {
                // ---- Rare CTA-wide B restage (fp16 fragment packing) ----
                __syncthreads();
                const float* W = kern + (size_t)kk * CIN * COUT;
                #pragma unroll
                for (int idx = tid; idx < CIN * COUT; idx += NTHREADS) {
                    int i = idx >> 6;              // cin
                    int o = idx & 63;              // cout
                    int P = o >> 4, local = o & 15;
                    int ttq = local >> 2, rr = local & 3;
                    int pos = (2 * P + (rr >> 1)) * 8 + 2 * ttq + (rr & 1);
                    int nt = pos >> 3, gg = pos & 7;
                    int sg = i >> 4, j = i & 15;
                    int tj = (j >> 1) & 3, e = j & 1, d = j >> 3;
                    uint32_t off = OFFB_B + (((nt * 4 + sg) * 32) + gg * 4 + tj) * 8
                                 + d * 4 + e * 2;
                    *(__half*)((char*)sh + off) = __float2half(W[idx]);
                }
                cur_k = kk;
                __syncthreads();
            }
            #pragma unroll
            for (int mt = 0; mt < 2; ++mt)
                #pragma unroll
                for (int nt = 0; nt < 4; ++nt)
                    #pragma unroll
                    for (int e = 0; e < 4; ++e) acc[mt][nt][e] = 0.f;
        }

        // ---- GEMM: 2 k16-steps per half-tile, conflict-free LDS.64 ----
        {
            uint32_t abase = shb + buf * ABUF_BYTES;
            #pragma unroll
            for (int sgl = 0; sgl < 2; ++sgl) {
                const int sg = h * 2 + sgl;
                const int chp = ((sgl * 2 + tsub) ^ gx) * 16 + toff;
                uint32_t a[2][4];
                #pragma unroll
                for (int mt = 0; mt < 2; ++mt) {
                    uint32_t addr = abase + (mbase + mt * 16 + g) * AB_STRIDE + chp;
                    asm volatile("ld.shared.v2.b32 {%0,%1}, [%2];"
                                 : "=r"(a[mt][0]), "=r"(a[mt][2]) : "r"(addr));
                    asm volatile("ld.shared.v2.b32 {%0,%1}, [%2];"
                                 : "=r"(a[mt][1]), "=r"(a[mt][3])
                                 : "r"(addr + 8 * AB_STRIDE));
                }
                #pragma unroll
                for (int nt = 0; nt < 4; ++nt) {
                    const int ntp = chalf * 4 + nt;
                    uint32_t b0, b1;
                    uint32_t baddr = shb + OFFB_B + ((ntp * 4 + sg) * 32 + lid) * 8;
                    asm volatile("ld.shared.v2.b32 {%0,%1}, [%2];"
                                 : "=r"(b0), "=r"(b1) : "r"(baddr));
                    mma16(acc[0][nt], a[0][0], a[0][1], a[0][2], a[0][3], b0, b1);
                    mma16(acc[1][nt], a[1][0], a[1][1], a[1][2], a[1][3], b0, b1);
                }
            }
        }

        if (h == 1) {
            // ---- Scatter: v4 global reductions, 4 contiguous couts each ----
            const int slot = li % 3;
            #pragma unroll
            for (int mt = 0; mt < 2; ++mt) {
                #pragma unroll
                for (int half = 0; half < 2; ++half) {
                    int ml = mbase + mt * 16 + g + half * 8;
                    int m = m0 + ml;
                    if (m < MPAIRS) {
                        int orow = (int)sh[OMAP_W + slot * TILE_M + ml];
                        float* dst = out + (size_t)orow * COUT + t * 4;
                        #pragma unroll
                        for (int pp = 0; pp < 2; ++pp) {
                            int P = chalf * 2 + pp;
                            asm volatile("red.global.add.v4.f32 [%0], {%1,%2,%3,%4};"
                                         :: "l"(dst + 16 * P),
                                            "f"(acc[mt][2 * pp][half * 2]),
                                            "f"(acc[mt][2 * pp][half * 2 + 1]),
                                            "f"(acc[mt][2 * pp + 1][half * 2]),
                                            "f"(acc[mt][2 * pp + 1][half * 2 + 1]) : "memory");
                        }
                    }
                }
            }
        }

        if (++buf == 3) buf = 0;
    }
}

extern "C" void kernel_launch(void* const* d_in, const int* in_sizes, int n_in,
                              void* d_out, int out_size) {
    const float* feats   = (const float*)d_in[0];   // [N, 64]
    const float* kern    = (const float*)d_in[1];   // [27, 64, 64]
    const int*   in_map  = (const int*)d_in[2];     // [27, 50000]
    const int*   out_map = (const int*)d_in[3];     // [27, 50000]
    float* out = (float*)d_out;                     // [N, 64]

    // Fused zero + fp32->fp16 permuted convert (same 3.2M-float4 index range).
    int n4 = NVOX * COUT / 4;
    spconv_init_kernel<<<(n4 + 255) / 256, 256>>>(feats, (float4*)out);

    cudaFuncSetAttribute(spconv_pers_kernel,
                         cudaFuncAttributeMaxDynamicSharedMemorySize, SMEM_BYTES);
    spconv_pers_kernel<<<NCTA, NTHREADS, SMEM_BYTES>>>(kern, in_map, out_map, out);
}